// round 1
// baseline (speedup 1.0000x reference)
#include <cuda_runtime.h>
#include <math.h>

#define NN 8192
#define EE 131072
#define DIM 32
#define HID 128
#define BG 64
#define NMP 3
#define S2S 3
#define KDIM 4096   // HID*DIM

// ---------------- scratch (device globals; no allocation) ----------------
__device__ float g_out[NN * DIM];          // node features (out == GRU hidden h)
__device__ float g_h[EE * HID];            // edge MLP hidden, relu(ea@w1+b1)   67MB
__device__ float g_P[(size_t)NN * KDIM];   // per-node accumulated outer prods 134MB
__device__ float g_usum[NN * DIM];
__device__ float g_aggpre[NN * DIM];
__device__ int   g_cnt[NN];
__device__ int   g_rowptr[NN + 1];
__device__ int   g_woff[NN];
__device__ int   g_eids[EE];
__device__ float g_deg[NN];
__device__ int   g_gptr[BG + 1];
__device__ float g_qh[BG * DIM];
__device__ float g_qc[BG * DIM];
__device__ float g_qstar[BG * 2 * DIM];

__device__ __forceinline__ float sigm(float x) { return 1.0f / (1.0f + expf(-x)); }

// ---------------- init / setup kernels ----------------
__global__ void k_zero_cnt() {
    int i = blockIdx.x * blockDim.x + threadIdx.x;
    if (i < NN) g_cnt[i] = 0;
}

__global__ void k_zero_s2s() {
    int i = blockIdx.x * blockDim.x + threadIdx.x;
    if (i < BG * DIM) { g_qh[i] = 0.f; g_qc[i] = 0.f; }
    if (i < BG * 2 * DIM) g_qstar[i] = 0.f;
}

__global__ void k_init_nodes(const float* __restrict__ x,
                             const float* __restrict__ w0,
                             const float* __restrict__ b0) {
    int idx = blockIdx.x * blockDim.x + threadIdx.x;
    if (idx >= NN * DIM) return;
    int n = idx >> 5, j = idx & 31;
    float v = x[n] * w0[j] + b0[j];
    g_out[idx] = v > 0.f ? v : 0.f;
}

__global__ void k_edge_hidden(const float* __restrict__ ea,
                              const float* __restrict__ w1,
                              const float* __restrict__ b1) {
    int idx = blockIdx.x * blockDim.x + threadIdx.x;
    if (idx >= EE * HID) return;
    int e = idx >> 7, k = idx & 127;
    float v = ea[2 * e] * __ldg(&w1[k]) + ea[2 * e + 1] * __ldg(&w1[HID + k]) + __ldg(&b1[k]);
    g_h[idx] = v > 0.f ? v : 0.f;
}

__global__ void k_count(const int* __restrict__ ei) {
    int e = blockIdx.x * blockDim.x + threadIdx.x;
    if (e < EE) atomicAdd(&g_cnt[ei[EE + e]], 1);
}

// single-block exclusive scan of g_cnt (8192) -> rowptr, woff, deg
__global__ void k_scan() {
    __shared__ int tot[1024];
    int t = threadIdx.x;
    int base = t * 8;
    int v[8]; int s = 0;
#pragma unroll
    for (int i = 0; i < 8; i++) { v[i] = g_cnt[base + i]; s += v[i]; }
    tot[t] = s;
    __syncthreads();
    for (int d = 1; d < 1024; d <<= 1) {
        int add = (t >= d) ? tot[t - d] : 0;
        __syncthreads();
        tot[t] += add;
        __syncthreads();
    }
    int run = tot[t] - s;  // exclusive prefix for this chunk
#pragma unroll
    for (int i = 0; i < 8; i++) {
        g_rowptr[base + i] = run;
        g_woff[base + i] = run;
        g_deg[base + i] = (float)(v[i] > 0 ? v[i] : 1);
        run += v[i];
    }
    if (t == 1023) g_rowptr[NN] = run;
}

__global__ void k_fill(const int* __restrict__ ei) {
    int e = blockIdx.x * blockDim.x + threadIdx.x;
    if (e >= EE) return;
    int dst = ei[EE + e];
    int pos = atomicAdd(&g_woff[dst], 1);
    g_eids[pos] = e;
}

__global__ void k_gptr(const int* __restrict__ batch) {
    int b = threadIdx.x;
    if (b > BG) return;
    int lo = 0, hi = NN;
    while (lo < hi) {
        int mid = (lo + hi) >> 1;
        if (batch[mid] < b) lo = mid + 1; else hi = mid;
    }
    g_gptr[b] = lo;
}

// ---------------- message passing ----------------
// one block per dst node: P[n] = sum_{e->n} h_e (128) outer u_src (32); also usum
__global__ void k_scatter(const int* __restrict__ ei) {
    int n = blockIdx.x;
    int k = threadIdx.x;  // 0..127
    __shared__ float su[4][DIM];
    __shared__ int se[4];
    int lo = g_rowptr[n], hi = g_rowptr[n + 1];
    float4 acc[8];
#pragma unroll
    for (int q = 0; q < 8; q++) acc[q] = make_float4(0.f, 0.f, 0.f, 0.f);
    float us = 0.f;
    for (int base = lo; base < hi; base += 4) {
        int m = hi - base; if (m > 4) m = 4;
        __syncthreads();
        if (k < m) se[k] = g_eids[base + k];
        __syncthreads();
        if (k < m * 32) {
            int g = k >> 5, d = k & 31;
            su[g][d] = g_out[ei[se[g]] * DIM + d];
        }
        __syncthreads();
        for (int j = 0; j < m; j++) {
            float hk = g_h[(size_t)se[j] * HID + k];
            const float4* su4 = (const float4*)su[j];
#pragma unroll
            for (int q = 0; q < 8; q++) {
                float4 b = su4[q];
                acc[q].x += hk * b.x; acc[q].y += hk * b.y;
                acc[q].z += hk * b.z; acc[q].w += hk * b.w;
            }
            if (k < 32) us += su[j][k];
        }
    }
    float4* Pp = (float4*)(g_P + (size_t)n * KDIM + k * DIM);
#pragma unroll
    for (int q = 0; q < 8; q++) Pp[q] = acc[q];
    if (k < 32) g_usum[n * DIM + k] = us;
}

// aggpre[N,32] = P[N,4096] @ w2flat[4096,32]
__global__ void k_gemm(const float* __restrict__ w2) {
    __shared__ float As[64][33];
    __shared__ float Bs[32][32];
    int tid = threadIdx.x;           // 256
    int tile = blockIdx.x;           // 128 tiles of 64 nodes
    int tr = tid >> 3;               // 0..31 (pairs of nodes)
    int tc = tid & 7;                // 0..7  (groups of 4 cols)
    float a00 = 0.f, a01 = 0.f, a02 = 0.f, a03 = 0.f;
    float a10 = 0.f, a11 = 0.f, a12 = 0.f, a13 = 0.f;
    for (int kc = 0; kc < KDIM; kc += 32) {
#pragma unroll
        for (int i = 0; i < 8; i++) {
            int lin = i * 256 + tid;
            int r = lin >> 5, c = lin & 31;
            As[r][c] = g_P[(size_t)(tile * 64 + r) * KDIM + kc + c];
        }
#pragma unroll
        for (int i = 0; i < 4; i++) {
            int lin = i * 256 + tid;
            Bs[lin >> 5][lin & 31] = w2[(size_t)kc * 32 + lin];
        }
        __syncthreads();
#pragma unroll
        for (int c = 0; c < 32; c++) {
            float x0 = As[tr * 2][c];
            float x1 = As[tr * 2 + 1][c];
            float4 b = *(const float4*)&Bs[c][tc * 4];
            a00 += x0 * b.x; a01 += x0 * b.y; a02 += x0 * b.z; a03 += x0 * b.w;
            a10 += x1 * b.x; a11 += x1 * b.y; a12 += x1 * b.z; a13 += x1 * b.w;
        }
        __syncthreads();
    }
    int n0 = tile * 64 + tr * 2;
    *(float4*)&g_aggpre[n0 * DIM + tc * 4] = make_float4(a00, a01, a02, a03);
    *(float4*)&g_aggpre[(n0 + 1) * DIM + tc * 4] = make_float4(a10, a11, a12, a13);
}

// per-node: agg=(aggpre + usum@B2)/deg ; m=relu(agg + out@root + cb) ; GRU update
__global__ void k_update(const float* __restrict__ b2,
                         const float* __restrict__ rootw,
                         const float* __restrict__ convb,
                         const float* __restrict__ wih,
                         const float* __restrict__ whh,
                         const float* __restrict__ bih,
                         const float* __restrict__ bhh) {
    __shared__ float Msm[8][DIM];
    int n = blockIdx.x * 8 + (threadIdx.x >> 5);
    int o = threadIdx.x & 31;
    int nl = threadIdx.x >> 5;

    float ub = 0.f;
#pragma unroll
    for (int d = 0; d < DIM; d++) ub += g_usum[n * DIM + d] * __ldg(&b2[d * DIM + o]);
    float agg = (g_aggpre[n * DIM + o] + ub) / g_deg[n];
    float mo = agg + __ldg(&convb[o]);
#pragma unroll
    for (int d = 0; d < DIM; d++) mo += g_out[n * DIM + d] * __ldg(&rootw[d * DIM + o]);
    mo = mo > 0.f ? mo : 0.f;
    Msm[nl][o] = mo;
    __syncthreads();

    float ir = __ldg(&bih[o]), iz = __ldg(&bih[32 + o]), inn = __ldg(&bih[64 + o]);
    float hr = __ldg(&bhh[o]), hz = __ldg(&bhh[32 + o]), hn = __ldg(&bhh[64 + o]);
#pragma unroll
    for (int d = 0; d < DIM; d++) {
        float md = Msm[nl][d];
        float hd = g_out[n * DIM + d];
        ir += md * __ldg(&wih[d * 96 + o]);
        iz += md * __ldg(&wih[d * 96 + 32 + o]);
        inn += md * __ldg(&wih[d * 96 + 64 + o]);
        hr += hd * __ldg(&whh[d * 96 + o]);
        hz += hd * __ldg(&whh[d * 96 + 32 + o]);
        hn += hd * __ldg(&whh[d * 96 + 64 + o]);
    }
    float r = sigm(ir + hr);
    float z = sigm(iz + hz);
    float nv = tanhf(inn + r * hn);
    float hold = g_out[n * DIM + o];
    float hnew = (1.f - z) * nv + z * hold;
    __syncwarp();
    g_out[n * DIM + o] = hnew;
}

// ---------------- Set2Set ----------------
__global__ void k_lstm(const float* __restrict__ wih,
                       const float* __restrict__ whh,
                       const float* __restrict__ bih,
                       const float* __restrict__ bhh) {
    __shared__ float gs[128];
    int b = blockIdx.x;
    int j = threadIdx.x;  // 0..127
    float g = __ldg(&bih[j]) + __ldg(&bhh[j]);
#pragma unroll
    for (int t = 0; t < 2 * DIM; t++) g += g_qstar[b * 2 * DIM + t] * __ldg(&wih[t * 128 + j]);
#pragma unroll
    for (int t = 0; t < DIM; t++) g += g_qh[b * DIM + t] * __ldg(&whh[t * 128 + j]);
    gs[j] = g;
    __syncthreads();
    if (j < 32) {
        float i_ = gs[j], f_ = gs[32 + j], gg = gs[64 + j], oo = gs[96 + j];
        float qc = sigm(f_) * g_qc[b * DIM + j] + sigm(i_) * tanhf(gg);
        g_qc[b * DIM + j] = qc;
        g_qh[b * DIM + j] = sigm(oo) * tanhf(qc);
    }
}

__global__ void k_attend() {
    __shared__ float sqh[32];
    __shared__ float ebuf[4096];
    __shared__ float wred[8];
    __shared__ float rpart[8][32];
    __shared__ float s_bmax, s_den;
    int b = blockIdx.x;
    int tid = threadIdx.x;
    int w = tid >> 5, lane = tid & 31;
    int lo = g_gptr[b], hi = g_gptr[b + 1];
    int cnt = hi - lo;
    if (tid < 32) sqh[tid] = g_qh[b * DIM + tid];
    __syncthreads();

    float mymax = -1e30f;
    for (int i = lo + w; i < hi; i += 8) {
        float v = g_out[(size_t)i * DIM + lane] * sqh[lane];
#pragma unroll
        for (int off = 16; off; off >>= 1) v += __shfl_xor_sync(0xffffffffu, v, off);
        if (lane == 0) ebuf[i - lo] = v;
        mymax = fmaxf(mymax, v);
    }
    if (lane == 0) wred[w] = mymax;
    __syncthreads();
    if (tid == 0) {
        float m = -1e30f;
        for (int q = 0; q < 8; q++) m = fmaxf(m, wred[q]);
        s_bmax = m;
    }
    __syncthreads();
    float bm = s_bmax;

    float s = 0.f;
    for (int idx = tid; idx < cnt; idx += 256) {
        float ev = expf(ebuf[idx] - bm);
        ebuf[idx] = ev;
        s += ev;
    }
#pragma unroll
    for (int off = 16; off; off >>= 1) s += __shfl_xor_sync(0xffffffffu, s, off);
    if (lane == 0) wred[w] = s;
    __syncthreads();
    if (tid == 0) {
        float t = 0.f;
        for (int q = 0; q < 8; q++) t += wred[q];
        s_den = t;
    }
    __syncthreads();
    float invden = (cnt > 0 && s_den > 0.f) ? 1.f / s_den : 0.f;

    float rl = 0.f;
    for (int i = lo + w; i < hi; i += 8) {
        float a = ebuf[i - lo] * invden;
        rl += a * g_out[(size_t)i * DIM + lane];
    }
    rpart[w][lane] = rl;
    __syncthreads();
    if (w == 0) {
        float r = 0.f;
#pragma unroll
        for (int q = 0; q < 8; q++) r += rpart[q][lane];
        g_qstar[b * 2 * DIM + 32 + lane] = r;
        g_qstar[b * 2 * DIM + lane] = sqh[lane];
    }
}

__global__ void k_final(const float* __restrict__ w1,
                        const float* __restrict__ b1,
                        const float* __restrict__ w2,
                        const float* __restrict__ b2,
                        float* __restrict__ yout) {
    int b = blockIdx.x;
    int j = threadIdx.x;  // 0..31
    float hj = __ldg(&b1[j]);
#pragma unroll
    for (int t = 0; t < 2 * DIM; t++) hj += g_qstar[b * 2 * DIM + t] * __ldg(&w1[t * DIM + j]);
    hj = hj > 0.f ? hj : 0.f;
    float v = hj * __ldg(&w2[j]);
#pragma unroll
    for (int off = 16; off; off >>= 1) v += __shfl_xor_sync(0xffffffffu, v, off);
    if (j == 0) yout[b] = v + __ldg(&b2[0]);
}

// ---------------- launch ----------------
extern "C" void kernel_launch(void* const* d_in, const int* in_sizes, int n_in,
                              void* d_out, int out_size) {
    const float* x       = (const float*)d_in[0];
    const float* ea      = (const float*)d_in[1];
    const float* lin0w   = (const float*)d_in[2];
    const float* lin0b   = (const float*)d_in[3];
    const float* ennw1   = (const float*)d_in[4];
    const float* ennb1   = (const float*)d_in[5];
    const float* ennw2   = (const float*)d_in[6];
    const float* ennb2   = (const float*)d_in[7];
    const float* rootw   = (const float*)d_in[8];
    const float* convb   = (const float*)d_in[9];
    const float* gruwih  = (const float*)d_in[10];
    const float* gruwhh  = (const float*)d_in[11];
    const float* grubih  = (const float*)d_in[12];
    const float* grubhh  = (const float*)d_in[13];
    const float* s2swih  = (const float*)d_in[14];
    const float* s2swhh  = (const float*)d_in[15];
    const float* s2sbih  = (const float*)d_in[16];
    const float* s2sbhh  = (const float*)d_in[17];
    const float* lin1w   = (const float*)d_in[18];
    const float* lin1b   = (const float*)d_in[19];
    const float* lin2w   = (const float*)d_in[20];
    const float* lin2b   = (const float*)d_in[21];
    const int*   ei      = (const int*)d_in[22];
    const int*   batch   = (const int*)d_in[23];
    float* yout = (float*)d_out;

    k_zero_cnt<<<(NN + 1023) / 1024, 1024>>>();
    k_init_nodes<<<(NN * DIM + 255) / 256, 256>>>(x, lin0w, lin0b);
    k_edge_hidden<<<(EE * HID + 255) / 256, 256>>>(ea, ennw1, ennb1);
    k_count<<<(EE + 255) / 256, 256>>>(ei);
    k_scan<<<1, 1024>>>();
    k_fill<<<(EE + 255) / 256, 256>>>(ei);
    k_gptr<<<1, 128>>>(batch);

    for (int it = 0; it < NMP; it++) {
        k_scatter<<<NN, 128>>>(ei);
        k_gemm<<<NN / 64, 256>>>(ennw2);
        k_update<<<NN / 8, 256>>>(ennb2, rootw, convb, gruwih, gruwhh, grubih, grubhh);
    }

    k_zero_s2s<<<8, 1024>>>();
    for (int s = 0; s < S2S; s++) {
        k_lstm<<<BG, 128>>>(s2swih, s2swhh, s2sbih, s2sbhh);
        k_attend<<<BG, 256>>>();
    }
    k_final<<<BG, 32>>>(lin1w, lin1b, lin2w, lin2b, yout);
}